// round 1
// baseline (speedup 1.0000x reference)
#include <cuda_runtime.h>
#include <math.h>

#define B 4
#define S 2048
#define D_MODEL 512
#define NHEAD 8
#define HEAD_DIM 64
#define M_ROWS (B * S)          // 8192
#define QKV_N (3 * D_MODEL)     // 1536

// ------------------------ device scratch (no allocation allowed) ------------
__device__ float g_qkv[M_ROWS * QKV_N];                 // [B*S, 1536]
__device__ float g_q[B * NHEAD * S * HEAD_DIM];         // [B,H,S,Hd]
__device__ float g_k[B * NHEAD * S * HEAD_DIM];
__device__ float g_v[B * NHEAD * S * HEAD_DIM];
__device__ float g_att[B * NHEAD * S * HEAD_DIM];       // [B,H,S,Hd]
__device__ float g_obsd[M_ROWS * D_MODEL];              // [B*S, 512]

// ------------------------ SGEMM: C[M,N] = A[M,K] @ B[K,N] + bias[N] ---------
// BM=BN=128, BK=8, TM=TN=8, 256 threads.
__global__ __launch_bounds__(256)
void sgemm_bias_kernel(const float* __restrict__ A,
                       const float* __restrict__ Bm,
                       const float* __restrict__ bias,
                       float* __restrict__ C,
                       int M, int N, int K)
{
    __shared__ float As[8][128];
    __shared__ float Bs[8][128];

    const int tid = threadIdx.x;
    const int mBase = blockIdx.y * 128;
    const int nBase = blockIdx.x * 128;

    const int threadRow = tid / 16;   // 0..15
    const int threadCol = tid % 16;   // 0..15

    // A tile load mapping: 128 rows x 8 cols = 1024 floats = 256 * float4
    const int aRow = tid / 2;         // 0..127
    const int aCol = tid % 2;         // 0..1 (each is a float4 of the 8-wide k)
    // B tile load mapping: 8 rows x 128 cols
    const int bRow = tid / 32;        // 0..7
    const int bCol = tid % 32;        // 0..31 (float4 index)

    float acc[8][8];
#pragma unroll
    for (int i = 0; i < 8; i++)
#pragma unroll
        for (int j = 0; j < 8; j++) acc[i][j] = 0.f;

    for (int k0 = 0; k0 < K; k0 += 8) {
        // load A (transposed into As[k][m])
        float4 a = *(const float4*)&A[(mBase + aRow) * K + k0 + aCol * 4];
        As[aCol * 4 + 0][aRow] = a.x;
        As[aCol * 4 + 1][aRow] = a.y;
        As[aCol * 4 + 2][aRow] = a.z;
        As[aCol * 4 + 3][aRow] = a.w;
        // load B
        float4 b = *(const float4*)&Bm[(k0 + bRow) * N + nBase + bCol * 4];
        *(float4*)&Bs[bRow][bCol * 4] = b;
        __syncthreads();

#pragma unroll
        for (int kk = 0; kk < 8; kk++) {
            float regM[8], regN[8];
            *(float4*)&regM[0] = *(const float4*)&As[kk][threadRow * 8];
            *(float4*)&regM[4] = *(const float4*)&As[kk][threadRow * 8 + 4];
            *(float4*)&regN[0] = *(const float4*)&Bs[kk][threadCol * 8];
            *(float4*)&regN[4] = *(const float4*)&Bs[kk][threadCol * 8 + 4];
#pragma unroll
            for (int i = 0; i < 8; i++)
#pragma unroll
                for (int j = 0; j < 8; j++)
                    acc[i][j] += regM[i] * regN[j];
        }
        __syncthreads();
    }

    // epilogue with bias
    float bv[8];
#pragma unroll
    for (int j = 0; j < 8; j++) bv[j] = bias[nBase + threadCol * 8 + j];
#pragma unroll
    for (int i = 0; i < 8; i++) {
        float out[8];
#pragma unroll
        for (int j = 0; j < 8; j++) out[j] = acc[i][j] + bv[j];
        float* cp = &C[(mBase + threadRow * 8 + i) * N + nBase + threadCol * 8];
        *(float4*)&cp[0] = *(const float4*)&out[0];
        *(float4*)&cp[4] = *(const float4*)&out[4];
    }
}

// ------------------------ RoPE + split qkv -> q,k,v [B,H,S,Hd] ---------------
// one thread per (b,s,h,pair)
__global__ __launch_bounds__(256)
void rope_split_kernel()
{
    int idx = blockIdx.x * blockDim.x + threadIdx.x;
    const int total = B * S * NHEAD * (HEAD_DIM / 2);
    if (idx >= total) return;

    int i = idx & 31;            // pair index 0..31
    int t = idx >> 5;
    int h = t & (NHEAD - 1);     // 0..7
    t >>= 3;
    int s = t & (S - 1);         // 0..2047
    int b = t >> 11;

    const int row = b * S + s;
    const int base = row * QKV_N + h * HEAD_DIM + 2 * i;

    float2 q = *(const float2*)&g_qkv[base];
    float2 k = *(const float2*)&g_qkv[base + D_MODEL];
    float2 v = *(const float2*)&g_qkv[base + 2 * D_MODEL];

    float inv_freq = __powf(10000.0f, -((float)(2 * i) / (float)HEAD_DIM));
    float angle = (float)s * inv_freq;
    float sn, cs;
    __sincosf(angle, &sn, &cs);

    float2 qr = make_float2(q.x * cs - q.y * sn, q.x * sn + q.y * cs);
    float2 kr = make_float2(k.x * cs - k.y * sn, k.x * sn + k.y * cs);

    const int obase = ((b * NHEAD + h) * S + s) * HEAD_DIM + 2 * i;
    *(float2*)&g_q[obase] = qr;
    *(float2*)&g_k[obase] = kr;
    *(float2*)&g_v[obase] = v;
}

// ------------------------ attention (flash-style online softmax) ------------
// grid: (S/32, B*H). block: 256 thr = 8 warps. each warp: 4 query rows.
// smem: Ks[64][66], Vs[64][66], qs[32][64], ps[32][64]  (dynamic, 50176 B)
#define KS_STRIDE 66
__global__ __launch_bounds__(256)
void attention_kernel()
{
    extern __shared__ float sm[];
    float* Ks = sm;                       // 64*66
    float* Vs = Ks + 64 * KS_STRIDE;      // 64*66
    float* qs = Vs + 64 * KS_STRIDE;      // 32*64
    float* ps = qs + 32 * 64;             // 32*64

    const int tid = threadIdx.x;
    const int w = tid >> 5;
    const int lane = tid & 31;
    const int bh = blockIdx.y;
    const int row0 = blockIdx.x * 32;
    const float* kbase = &g_k[(size_t)bh * S * HEAD_DIM];
    const float* vbase = &g_v[(size_t)bh * S * HEAD_DIM];

    // load 32 query rows, pre-scaled by 1/sqrt(Hd)
    for (int idx = tid; idx < 32 * 64; idx += 256) {
        int r = idx >> 6, d = idx & 63;
        qs[r * 64 + d] = g_q[((size_t)bh * S + row0 + r) * HEAD_DIM + d] * 0.125f;
    }

    float m[4], l[4], acc[4][2];
#pragma unroll
    for (int r = 0; r < 4; r++) {
        m[r] = -1e30f; l[r] = 0.f; acc[r][0] = 0.f; acc[r][1] = 0.f;
    }

    for (int t = 0; t < S / 64; t++) {
        __syncthreads();
        // load K/V tile (64 keys x 64 dims), padded stride 66
        for (int idx = tid; idx < 64 * 64; idx += 256) {
            int r = idx >> 6, d = idx & 63;
            Ks[r * KS_STRIDE + d] = kbase[(size_t)(t * 64 + r) * HEAD_DIM + d];
            Vs[r * KS_STRIDE + d] = vbase[(size_t)(t * 64 + r) * HEAD_DIM + d];
        }
        __syncthreads();

        // phase A: scores. lane owns keys (lane, lane+32)
        float sc[4][2];
#pragma unroll
        for (int r = 0; r < 4; r++) { sc[r][0] = 0.f; sc[r][1] = 0.f; }
#pragma unroll
        for (int d2 = 0; d2 < 32; d2++) {
            float2 k0 = *(const float2*)&Ks[lane * KS_STRIDE + 2 * d2];
            float2 k1 = *(const float2*)&Ks[(lane + 32) * KS_STRIDE + 2 * d2];
#pragma unroll
            for (int r = 0; r < 4; r++) {
                float2 q = *(const float2*)&qs[(w * 4 + r) * 64 + 2 * d2];
                sc[r][0] += q.x * k0.x + q.y * k0.y;
                sc[r][1] += q.x * k1.x + q.y * k1.y;
            }
        }

        // phase B: online softmax update
#pragma unroll
        for (int r = 0; r < 4; r++) {
            float tmax = fmaxf(sc[r][0], sc[r][1]);
#pragma unroll
            for (int off = 16; off; off >>= 1)
                tmax = fmaxf(tmax, __shfl_xor_sync(0xffffffffu, tmax, off));
            float mn = fmaxf(m[r], tmax);
            float corr = __expf(m[r] - mn);
            float p0 = __expf(sc[r][0] - mn);
            float p1 = __expf(sc[r][1] - mn);
            float ls = p0 + p1;
#pragma unroll
            for (int off = 16; off; off >>= 1)
                ls += __shfl_xor_sync(0xffffffffu, ls, off);
            l[r] = l[r] * corr + ls;
            acc[r][0] *= corr;
            acc[r][1] *= corr;
            m[r] = mn;
            ps[(w * 4 + r) * 64 + lane] = p0;
            ps[(w * 4 + r) * 64 + lane + 32] = p1;
        }
        __syncwarp();

        // phase C: PV. lane owns output dims (2*lane, 2*lane+1)
#pragma unroll
        for (int j = 0; j < 64; j++) {
            float2 v = *(const float2*)&Vs[j * KS_STRIDE + 2 * lane];
#pragma unroll
            for (int r = 0; r < 4; r++) {
                float p = ps[(w * 4 + r) * 64 + j];
                acc[r][0] += p * v.x;
                acc[r][1] += p * v.y;
            }
        }
    }

    // write out [B,H,S,Hd]
#pragma unroll
    for (int r = 0; r < 4; r++) {
        int row = row0 + w * 4 + r;
        float inv_l = 1.0f / l[r];
        float2 o = make_float2(acc[r][0] * inv_l, acc[r][1] * inv_l);
        *(float2*)&g_att[((size_t)bh * S + row) * HEAD_DIM + 2 * lane] = o;
    }
}

// ------------------------ [B,H,S,Hd] -> [B,S,D] transpose -------------------
__global__ __launch_bounds__(256)
void merge_heads_kernel()
{
    int idx = blockIdx.x * blockDim.x + threadIdx.x;
    const int total = M_ROWS * D_MODEL;
    if (idx >= total) return;
    int dm = idx & (D_MODEL - 1);
    int mrow = idx >> 9;
    int s = mrow & (S - 1);
    int b = mrow >> 11;
    int h = dm >> 6;
    int d = dm & 63;
    g_obsd[idx] = g_att[(((size_t)(b * NHEAD + h)) * S + s) * HEAD_DIM + d];
}

// ------------------------ launch ---------------------------------------------
extern "C" void kernel_launch(void* const* d_in, const int* in_sizes, int n_in,
                              void* d_out, int out_size)
{
    const float* x    = (const float*)d_in[0];
    const float* Wqkv = (const float*)d_in[1];
    const float* bqkv = (const float*)d_in[2];
    const float* Wo   = (const float*)d_in[3];
    const float* bo   = (const float*)d_in[4];
    float* out = (float*)d_out;

    float *p_qkv, *p_obsd;
    cudaGetSymbolAddress((void**)&p_qkv, g_qkv);
    cudaGetSymbolAddress((void**)&p_obsd, g_obsd);

    // 1) QKV projection
    {
        dim3 grid(QKV_N / 128, M_ROWS / 128);
        sgemm_bias_kernel<<<grid, 256>>>(x, Wqkv, bqkv, p_qkv,
                                         M_ROWS, QKV_N, D_MODEL);
    }
    // 2) RoPE + split
    {
        int total = B * S * NHEAD * (HEAD_DIM / 2);
        rope_split_kernel<<<(total + 255) / 256, 256>>>();
    }
    // 3) attention
    {
        const int smem = (2 * 64 * KS_STRIDE + 2 * 32 * 64) * (int)sizeof(float);
        cudaFuncSetAttribute(attention_kernel,
                             cudaFuncAttributeMaxDynamicSharedMemorySize, smem);
        dim3 grid(S / 32, B * NHEAD);
        attention_kernel<<<grid, 256, smem>>>();
    }
    // 4) merge heads
    {
        int total = M_ROWS * D_MODEL;
        merge_heads_kernel<<<(total + 255) / 256, 256>>>();
    }
    // 5) output projection
    {
        dim3 grid(D_MODEL / 128, M_ROWS / 128);
        sgemm_bias_kernel<<<grid, 256>>>(p_obsd, Wo, bo, out,
                                         M_ROWS, D_MODEL, D_MODEL);
    }
}

// round 2
// speedup vs baseline: 3.3875x; 3.3875x over previous
#include <cuda_runtime.h>
#include <math.h>
#include <stdint.h>

#define BATCH 4
#define SEQ 2048
#define D_MODEL 512
#define NHEAD 8
#define HEAD_DIM 64
#define M_ROWS (BATCH * SEQ)      // 8192
#define QKV_N (3 * D_MODEL)       // 1536
#define K_DIM 512

// ------------------------ device scratch -----------------------------------
__device__ float g_q[BATCH * NHEAD * SEQ * HEAD_DIM];
__device__ float g_k[BATCH * NHEAD * SEQ * HEAD_DIM];
__device__ float g_v[BATCH * NHEAD * SEQ * HEAD_DIM];
__device__ float g_att[M_ROWS * D_MODEL];          // attention out, [B,S,D]
__device__ float g_wqkvt[QKV_N * K_DIM];           // Wqkv^T  [1536][512]
__device__ float g_wot[D_MODEL * D_MODEL];         // Wo^T    [512][512]

// ------------------------ helpers ------------------------------------------
__device__ __forceinline__ float tf32r(float x) {
    uint32_t u;
    asm("cvt.rna.tf32.f32 %0, %1;" : "=r"(u) : "f"(x));
    return __uint_as_float(u);
}

__device__ __forceinline__ void mma_tf32(float c[4], const uint32_t a[4],
                                         uint32_t b0, uint32_t b1) {
    asm volatile(
        "mma.sync.aligned.m16n8k8.row.col.f32.tf32.tf32.f32 "
        "{%0,%1,%2,%3}, {%4,%5,%6,%7}, {%8,%9}, {%0,%1,%2,%3};\n"
        : "+f"(c[0]), "+f"(c[1]), "+f"(c[2]), "+f"(c[3])
        : "r"(a[0]), "r"(a[1]), "r"(a[2]), "r"(a[3]), "r"(b0), "r"(b1));
}

// ------------------------ transpose: in[R][C] -> out[C][R] ------------------
__global__ __launch_bounds__(256)
void transpose_kernel(const float* __restrict__ in, float* __restrict__ out,
                      int R, int C)
{
    __shared__ float tile[32][33];
    int cBase = blockIdx.x * 32, rBase = blockIdx.y * 32;
    int tx = threadIdx.x, ty = threadIdx.y;
#pragma unroll
    for (int i = 0; i < 32; i += 8)
        tile[ty + i][tx] = in[(size_t)(rBase + ty + i) * C + cBase + tx];
    __syncthreads();
#pragma unroll
    for (int i = 0; i < 32; i += 8)
        out[(size_t)(cBase + ty + i) * R + rBase + tx] = tile[tx][ty + i];
}

// ------------------------ tf32 GEMM ----------------------------------------
// C[M,N] = A[M,512] @ Bt[N,512]^T + bias.  BM=BN=128, BK=32.
// MODE 0: plain store to C (row-major, width N).
// MODE 1: QKV epilogue: RoPE on q/k regions, scatter into g_q/g_k/g_v [B,H,S,Hd].
template <int MODE>
__global__ __launch_bounds__(256, 2)
void gemm_tf32(const float* __restrict__ A, const float* __restrict__ Bt,
               const float* __restrict__ bias, float* __restrict__ C, int N)
{
    __shared__ float As[128][36];
    __shared__ float Bs[128][36];

    const int tid = threadIdx.x;
    const int lane = tid & 31;
    const int warp = tid >> 5;
    const int wm = warp >> 2;     // 0..1
    const int wn = warp & 3;      // 0..3
    const int lr = lane >> 2;     // 0..7
    const int lc = lane & 3;      // 0..3
    const int mBase = blockIdx.y * 128;
    const int nBase = blockIdx.x * 128;

    float acc[4][4][4];
#pragma unroll
    for (int mt = 0; mt < 4; mt++)
#pragma unroll
        for (int nt = 0; nt < 4; nt++)
#pragma unroll
            for (int j = 0; j < 4; j++) acc[mt][nt][j] = 0.f;

    const int cpRow = tid >> 3;   // 0..31
    const int cpC4 = tid & 7;     // 0..7

    for (int k0 = 0; k0 < K_DIM; k0 += 32) {
        __syncthreads();
#pragma unroll
        for (int i = 0; i < 4; i++) {
            int row = cpRow + i * 32;
            float4 va = *(const float4*)&A[(size_t)(mBase + row) * K_DIM + k0 + cpC4 * 4];
            va.x = tf32r(va.x); va.y = tf32r(va.y); va.z = tf32r(va.z); va.w = tf32r(va.w);
            *(float4*)&As[row][cpC4 * 4] = va;
            float4 vb = *(const float4*)&Bt[(size_t)(nBase + row) * K_DIM + k0 + cpC4 * 4];
            vb.x = tf32r(vb.x); vb.y = tf32r(vb.y); vb.z = tf32r(vb.z); vb.w = tf32r(vb.w);
            *(float4*)&Bs[row][cpC4 * 4] = vb;
        }
        __syncthreads();

#pragma unroll
        for (int kk = 0; kk < 4; kk++) {
            const int kb = kk * 8;
            uint32_t af[4][4];
#pragma unroll
            for (int mt = 0; mt < 4; mt++) {
                int r = wm * 64 + mt * 16 + lr;
                af[mt][0] = __float_as_uint(As[r][kb + lc]);
                af[mt][1] = __float_as_uint(As[r + 8][kb + lc]);
                af[mt][2] = __float_as_uint(As[r][kb + lc + 4]);
                af[mt][3] = __float_as_uint(As[r + 8][kb + lc + 4]);
            }
#pragma unroll
            for (int nt = 0; nt < 4; nt++) {
                int cn = wn * 32 + nt * 8 + lr;
                uint32_t b0 = __float_as_uint(Bs[cn][kb + lc]);
                uint32_t b1 = __float_as_uint(Bs[cn][kb + lc + 4]);
#pragma unroll
                for (int mt = 0; mt < 4; mt++)
                    mma_tf32(acc[mt][nt], af[mt], b0, b1);
            }
        }
    }

    // epilogue
#pragma unroll
    for (int mt = 0; mt < 4; mt++) {
#pragma unroll
        for (int nt = 0; nt < 4; nt++) {
            int grow0 = mBase + wm * 64 + mt * 16 + lr;
            int gcol = nBase + wn * 32 + nt * 8 + 2 * lc;
            float b0v = bias[gcol], b1v = bias[gcol + 1];
            if (MODE == 0) {
                *(float2*)&C[(size_t)grow0 * N + gcol] =
                    make_float2(acc[mt][nt][0] + b0v, acc[mt][nt][1] + b1v);
                *(float2*)&C[(size_t)(grow0 + 8) * N + gcol] =
                    make_float2(acc[mt][nt][2] + b0v, acc[mt][nt][3] + b1v);
            } else {
                int region = gcol >> 9;          // 0=q, 1=k, 2=v
                int h = (gcol >> 6) & 7;
                int d = gcol & 63;               // even
#pragma unroll
                for (int rr = 0; rr < 2; rr++) {
                    int grow = grow0 + rr * 8;
                    int bb = grow >> 11;
                    int ss = grow & (SEQ - 1);
                    float x1 = acc[mt][nt][2 * rr] + b0v;
                    float x2 = acc[mt][nt][2 * rr + 1] + b1v;
                    float* dst;
                    if (region == 2) {
                        dst = g_v;
                    } else {
                        float inv_freq = __powf(10000.f, -(float)d * (1.f / 64.f));
                        float sn, cs;
                        __sincosf((float)ss * inv_freq, &sn, &cs);
                        float r1 = x1 * cs - x2 * sn;
                        float r2 = x1 * sn + x2 * cs;
                        x1 = r1; x2 = r2;
                        dst = (region == 0) ? g_q : g_k;
                    }
                    *(float2*)&dst[(size_t)((bb * NHEAD + h) * SEQ + ss) * HEAD_DIM + d] =
                        make_float2(x1, x2);
                }
            }
        }
    }
}

// ------------------------ attention (tf32 mma, flash-style) -----------------
// grid (SEQ/128, B*H), 256 threads. Warp w owns 16 query rows. Output straight
// into g_att as [B,S,D].
#define QS 68
#define KSS 68
#define VSS 72
#define PSS 68
#define ATT_SMEM ((128*QS + 64*KSS + 64*VSS + 128*PSS) * 4)

__global__ __launch_bounds__(256, 1)
void attention_tf32()
{
    extern __shared__ float sm[];
    float* Qs = sm;                      // 128 x 68
    float* Ks = Qs + 128 * QS;           // 64 x 68
    float* Vs = Ks + 64 * KSS;           // 64 x 72
    float* Ps = Vs + 64 * VSS;           // 128 x 68

    const int tid = threadIdx.x;
    const int lane = tid & 31;
    const int w = tid >> 5;
    const int lr = lane >> 2;
    const int lc = lane & 3;
    const int bh = blockIdx.y;
    const int bb = bh >> 3, hh = bh & 7;
    const int row0 = blockIdx.x * 128;

    const float* qg = &g_q[(size_t)bh * SEQ * HEAD_DIM];
    const float* kg = &g_k[(size_t)bh * SEQ * HEAD_DIM];
    const float* vg = &g_v[(size_t)bh * SEQ * HEAD_DIM];

    // load Q (scaled by 1/sqrt(Hd), tf32-rounded)
#pragma unroll
    for (int i = 0; i < 8; i++) {
        int idx = tid + 256 * i;
        int row = idx >> 4, c4 = idx & 15;
        float4 v = *(const float4*)&qg[(size_t)(row0 + row) * HEAD_DIM + c4 * 4];
        v.x = tf32r(v.x * 0.125f); v.y = tf32r(v.y * 0.125f);
        v.z = tf32r(v.z * 0.125f); v.w = tf32r(v.w * 0.125f);
        *(float4*)&Qs[row * QS + c4 * 4] = v;
    }

    float o[8][4];
#pragma unroll
    for (int nt = 0; nt < 8; nt++)
#pragma unroll
        for (int j = 0; j < 4; j++) o[nt][j] = 0.f;
    float m0 = -1e30f, m1 = -1e30f, l0 = 0.f, l1 = 0.f;
    const int r0 = w * 16 + lr;

    for (int t = 0; t < SEQ / 64; t++) {
        __syncthreads();
#pragma unroll
        for (int i = 0; i < 4; i++) {
            int idx = tid + 256 * i;
            int row = idx >> 4, c4 = idx & 15;
            float4 kv = *(const float4*)&kg[(size_t)(t * 64 + row) * HEAD_DIM + c4 * 4];
            kv.x = tf32r(kv.x); kv.y = tf32r(kv.y); kv.z = tf32r(kv.z); kv.w = tf32r(kv.w);
            *(float4*)&Ks[row * KSS + c4 * 4] = kv;
            float4 vv = *(const float4*)&vg[(size_t)(t * 64 + row) * HEAD_DIM + c4 * 4];
            vv.x = tf32r(vv.x); vv.y = tf32r(vv.y); vv.z = tf32r(vv.z); vv.w = tf32r(vv.w);
            *(float4*)&Vs[row * VSS + c4 * 4] = vv;
        }
        __syncthreads();

        // ---- scores: Sc[16 x 64] = Q @ K^T
        float sc[8][4];
#pragma unroll
        for (int nt = 0; nt < 8; nt++)
#pragma unroll
            for (int j = 0; j < 4; j++) sc[nt][j] = 0.f;

#pragma unroll
        for (int kk = 0; kk < 8; kk++) {
            int kb = kk * 8;
            uint32_t a[4];
            a[0] = __float_as_uint(Qs[r0 * QS + kb + lc]);
            a[1] = __float_as_uint(Qs[(r0 + 8) * QS + kb + lc]);
            a[2] = __float_as_uint(Qs[r0 * QS + kb + lc + 4]);
            a[3] = __float_as_uint(Qs[(r0 + 8) * QS + kb + lc + 4]);
#pragma unroll
            for (int nt = 0; nt < 8; nt++) {
                uint32_t b0 = __float_as_uint(Ks[(nt * 8 + lr) * KSS + kb + lc]);
                uint32_t b1 = __float_as_uint(Ks[(nt * 8 + lr) * KSS + kb + lc + 4]);
                mma_tf32(sc[nt], a, b0, b1);
            }
        }

        // ---- online softmax
        float rmax0 = -1e30f, rmax1 = -1e30f;
#pragma unroll
        for (int nt = 0; nt < 8; nt++) {
            rmax0 = fmaxf(rmax0, fmaxf(sc[nt][0], sc[nt][1]));
            rmax1 = fmaxf(rmax1, fmaxf(sc[nt][2], sc[nt][3]));
        }
        rmax0 = fmaxf(rmax0, __shfl_xor_sync(0xffffffffu, rmax0, 1));
        rmax0 = fmaxf(rmax0, __shfl_xor_sync(0xffffffffu, rmax0, 2));
        rmax1 = fmaxf(rmax1, __shfl_xor_sync(0xffffffffu, rmax1, 1));
        rmax1 = fmaxf(rmax1, __shfl_xor_sync(0xffffffffu, rmax1, 2));

        float mn0 = fmaxf(m0, rmax0), mn1 = fmaxf(m1, rmax1);
        float corr0 = __expf(m0 - mn0), corr1 = __expf(m1 - mn1);
        float ls0 = 0.f, ls1 = 0.f;
#pragma unroll
        for (int nt = 0; nt < 8; nt++) {
            float p0 = __expf(sc[nt][0] - mn0);
            float p1 = __expf(sc[nt][1] - mn0);
            float p2 = __expf(sc[nt][2] - mn1);
            float p3 = __expf(sc[nt][3] - mn1);
            ls0 += p0 + p1;
            ls1 += p2 + p3;
            *(float2*)&Ps[r0 * PSS + nt * 8 + 2 * lc] = make_float2(tf32r(p0), tf32r(p1));
            *(float2*)&Ps[(r0 + 8) * PSS + nt * 8 + 2 * lc] = make_float2(tf32r(p2), tf32r(p3));
        }
        ls0 += __shfl_xor_sync(0xffffffffu, ls0, 1);
        ls0 += __shfl_xor_sync(0xffffffffu, ls0, 2);
        ls1 += __shfl_xor_sync(0xffffffffu, ls1, 1);
        ls1 += __shfl_xor_sync(0xffffffffu, ls1, 2);
        l0 = l0 * corr0 + ls0;
        l1 = l1 * corr1 + ls1;
        m0 = mn0; m1 = mn1;
#pragma unroll
        for (int nt = 0; nt < 8; nt++) {
            o[nt][0] *= corr0; o[nt][1] *= corr0;
            o[nt][2] *= corr1; o[nt][3] *= corr1;
        }
        __syncwarp();

        // ---- O += P @ V
#pragma unroll
        for (int kk = 0; kk < 8; kk++) {
            int kb = kk * 8;
            uint32_t a[4];
            a[0] = __float_as_uint(Ps[r0 * PSS + kb + lc]);
            a[1] = __float_as_uint(Ps[(r0 + 8) * PSS + kb + lc]);
            a[2] = __float_as_uint(Ps[r0 * PSS + kb + lc + 4]);
            a[3] = __float_as_uint(Ps[(r0 + 8) * PSS + kb + lc + 4]);
#pragma unroll
            for (int nt = 0; nt < 8; nt++) {
                uint32_t b0 = __float_as_uint(Vs[(kb + lc) * VSS + nt * 8 + lr]);
                uint32_t b1 = __float_as_uint(Vs[(kb + lc + 4) * VSS + nt * 8 + lr]);
                mma_tf32(o[nt], a, b0, b1);
            }
        }
    }

    // epilogue: write [B,S,D]
    float il0 = 1.f / l0, il1 = 1.f / l1;
    int srow = row0 + r0;
#pragma unroll
    for (int nt = 0; nt < 8; nt++) {
        int d = hh * 64 + nt * 8 + 2 * lc;
        *(float2*)&g_att[(size_t)(bb * SEQ + srow) * D_MODEL + d] =
            make_float2(o[nt][0] * il0, o[nt][1] * il0);
        *(float2*)&g_att[(size_t)(bb * SEQ + srow + 8) * D_MODEL + d] =
            make_float2(o[nt][2] * il1, o[nt][3] * il1);
    }
}

// ------------------------ launch --------------------------------------------
extern "C" void kernel_launch(void* const* d_in, const int* in_sizes, int n_in,
                              void* d_out, int out_size)
{
    const float* x    = (const float*)d_in[0];
    const float* Wqkv = (const float*)d_in[1];
    const float* bqkv = (const float*)d_in[2];
    const float* Wo   = (const float*)d_in[3];
    const float* bo   = (const float*)d_in[4];
    float* out = (float*)d_out;

    float *p_att, *p_wqkvt, *p_wot;
    cudaGetSymbolAddress((void**)&p_att, g_att);
    cudaGetSymbolAddress((void**)&p_wqkvt, g_wqkvt);
    cudaGetSymbolAddress((void**)&p_wot, g_wot);

    // transpose weights -> [N][K]
    {
        dim3 blk(32, 8);
        transpose_kernel<<<dim3(QKV_N / 32, K_DIM / 32), blk>>>(Wqkv, p_wqkvt, K_DIM, QKV_N);
        transpose_kernel<<<dim3(D_MODEL / 32, K_DIM / 32), blk>>>(Wo, p_wot, K_DIM, D_MODEL);
    }
    // QKV projection + RoPE + split
    {
        dim3 grid(QKV_N / 128, M_ROWS / 128);
        gemm_tf32<1><<<grid, 256>>>(x, p_wqkvt, bqkv, nullptr, QKV_N);
    }
    // attention
    {
        cudaFuncSetAttribute(attention_tf32,
                             cudaFuncAttributeMaxDynamicSharedMemorySize, ATT_SMEM);
        dim3 grid(SEQ / 128, BATCH * NHEAD);
        attention_tf32<<<grid, 256, ATT_SMEM>>>();
    }
    // output projection
    {
        dim3 grid(D_MODEL / 128, M_ROWS / 128);
        gemm_tf32<0><<<grid, 256>>>(p_att, p_wot, bo, out, D_MODEL);
    }
}

// round 3
// speedup vs baseline: 4.3571x; 1.2862x over previous
#include <cuda_runtime.h>
#include <math.h>
#include <stdint.h>

#define BATCH 4
#define SEQ 2048
#define D_MODEL 512
#define NHEAD 8
#define HEAD_DIM 64
#define M_ROWS (BATCH * SEQ)      // 8192
#define QKV_N (3 * D_MODEL)       // 1536
#define K_DIM 512

// ------------------------ device scratch -----------------------------------
__device__ float g_q[BATCH * NHEAD * SEQ * HEAD_DIM];
__device__ float g_k[BATCH * NHEAD * SEQ * HEAD_DIM];
__device__ float g_v[BATCH * NHEAD * SEQ * HEAD_DIM];
__device__ float g_att[M_ROWS * D_MODEL];          // attention out, [B,S,D]
__device__ float g_wqkvt[QKV_N * K_DIM];           // Wqkv^T  [1536][512]
__device__ float g_wot[D_MODEL * D_MODEL];         // Wo^T    [512][512]

// ------------------------ helpers ------------------------------------------
__device__ __forceinline__ float tf32r(float x) {
    uint32_t u;
    asm("cvt.rna.tf32.f32 %0, %1;" : "=r"(u) : "f"(x));
    return __uint_as_float(u);
}

__device__ __forceinline__ float ex2f(float x) {
    float y;
    asm("ex2.approx.f32 %0, %1;" : "=f"(y) : "f"(x));
    return y;
}

__device__ __forceinline__ void mma_tf32(float c[4], const uint32_t a[4],
                                         uint32_t b0, uint32_t b1) {
    asm volatile(
        "mma.sync.aligned.m16n8k8.row.col.f32.tf32.tf32.f32 "
        "{%0,%1,%2,%3}, {%4,%5,%6,%7}, {%8,%9}, {%0,%1,%2,%3};\n"
        : "+f"(c[0]), "+f"(c[1]), "+f"(c[2]), "+f"(c[3])
        : "r"(a[0]), "r"(a[1]), "r"(a[2]), "r"(a[3]), "r"(b0), "r"(b1));
}

__device__ __forceinline__ unsigned smem_u32(const void* p) {
    return (unsigned)__cvta_generic_to_shared(p);
}

#define CP_ASYNC16(dst_u32, src_ptr) \
    asm volatile("cp.async.cg.shared.global [%0], [%1], 16;\n" \
                 :: "r"(dst_u32), "l"(src_ptr) : "memory")

// ------------------------ transpose: in[R][C] -> out[C][R] ------------------
__global__ __launch_bounds__(256)
void transpose_kernel(const float* __restrict__ in, float* __restrict__ out,
                      int R, int C)
{
    __shared__ float tile[32][33];
    int cBase = blockIdx.x * 32, rBase = blockIdx.y * 32;
    int tx = threadIdx.x, ty = threadIdx.y;
#pragma unroll
    for (int i = 0; i < 32; i += 8)
        tile[ty + i][tx] = in[(size_t)(rBase + ty + i) * C + cBase + tx];
    __syncthreads();
#pragma unroll
    for (int i = 0; i < 32; i += 8)
        out[(size_t)(cBase + ty + i) * R + rBase + tx] = tile[tx][ty + i];
}

// ------------------------ tf32 GEMM ----------------------------------------
// C[M,N] = A[M,512] @ Bt[N,512]^T + bias.  BM=BN=128, BK=32.
// MODE 0: plain store to C (row-major, width N).
// MODE 1: QKV epilogue: RoPE on q/k, tf32-round q/k/v, scatter to [B,H,S,Hd].
template <int MODE>
__global__ __launch_bounds__(256, 2)
void gemm_tf32(const float* __restrict__ A, const float* __restrict__ Bt,
               const float* __restrict__ bias, float* __restrict__ C, int N)
{
    __shared__ float As[128][36];
    __shared__ float Bs[128][36];

    const int tid = threadIdx.x;
    const int lane = tid & 31;
    const int warp = tid >> 5;
    const int wm = warp >> 2;
    const int wn = warp & 3;
    const int lr = lane >> 2;
    const int lc = lane & 3;
    const int mBase = blockIdx.y * 128;
    const int nBase = blockIdx.x * 128;

    float acc[4][4][4];
#pragma unroll
    for (int mt = 0; mt < 4; mt++)
#pragma unroll
        for (int nt = 0; nt < 4; nt++)
#pragma unroll
            for (int j = 0; j < 4; j++) acc[mt][nt][j] = 0.f;

    const int cpRow = tid >> 3;
    const int cpC4 = tid & 7;

    for (int k0 = 0; k0 < K_DIM; k0 += 32) {
        __syncthreads();
#pragma unroll
        for (int i = 0; i < 4; i++) {
            int row = cpRow + i * 32;
            float4 va = *(const float4*)&A[(size_t)(mBase + row) * K_DIM + k0 + cpC4 * 4];
            va.x = tf32r(va.x); va.y = tf32r(va.y); va.z = tf32r(va.z); va.w = tf32r(va.w);
            *(float4*)&As[row][cpC4 * 4] = va;
            float4 vb = *(const float4*)&Bt[(size_t)(nBase + row) * K_DIM + k0 + cpC4 * 4];
            vb.x = tf32r(vb.x); vb.y = tf32r(vb.y); vb.z = tf32r(vb.z); vb.w = tf32r(vb.w);
            *(float4*)&Bs[row][cpC4 * 4] = vb;
        }
        __syncthreads();

#pragma unroll
        for (int kk = 0; kk < 4; kk++) {
            const int kb = kk * 8;
            uint32_t af[4][4];
#pragma unroll
            for (int mt = 0; mt < 4; mt++) {
                int r = wm * 64 + mt * 16 + lr;
                af[mt][0] = __float_as_uint(As[r][kb + lc]);
                af[mt][1] = __float_as_uint(As[r + 8][kb + lc]);
                af[mt][2] = __float_as_uint(As[r][kb + lc + 4]);
                af[mt][3] = __float_as_uint(As[r + 8][kb + lc + 4]);
            }
#pragma unroll
            for (int nt = 0; nt < 4; nt++) {
                int cn = wn * 32 + nt * 8 + lr;
                uint32_t b0 = __float_as_uint(Bs[cn][kb + lc]);
                uint32_t b1 = __float_as_uint(Bs[cn][kb + lc + 4]);
#pragma unroll
                for (int mt = 0; mt < 4; mt++)
                    mma_tf32(acc[mt][nt], af[mt], b0, b1);
            }
        }
    }

#pragma unroll
    for (int mt = 0; mt < 4; mt++) {
#pragma unroll
        for (int nt = 0; nt < 4; nt++) {
            int grow0 = mBase + wm * 64 + mt * 16 + lr;
            int gcol = nBase + wn * 32 + nt * 8 + 2 * lc;
            float b0v = bias[gcol], b1v = bias[gcol + 1];
            if (MODE == 0) {
                *(float2*)&C[(size_t)grow0 * N + gcol] =
                    make_float2(acc[mt][nt][0] + b0v, acc[mt][nt][1] + b1v);
                *(float2*)&C[(size_t)(grow0 + 8) * N + gcol] =
                    make_float2(acc[mt][nt][2] + b0v, acc[mt][nt][3] + b1v);
            } else {
                int region = gcol >> 9;          // 0=q, 1=k, 2=v
                int h = (gcol >> 6) & 7;
                int d = gcol & 63;               // even
#pragma unroll
                for (int rr = 0; rr < 2; rr++) {
                    int grow = grow0 + rr * 8;
                    int bb = grow >> 11;
                    int ss = grow & (SEQ - 1);
                    float x1 = acc[mt][nt][2 * rr] + b0v;
                    float x2 = acc[mt][nt][2 * rr + 1] + b1v;
                    float* dst;
                    if (region == 2) {
                        dst = g_v;
                    } else {
                        float inv_freq = __powf(10000.f, -(float)d * (1.f / 64.f));
                        float sn, cs;
                        __sincosf((float)ss * inv_freq, &sn, &cs);
                        float r1 = x1 * cs - x2 * sn;
                        float r2 = x1 * sn + x2 * cs;
                        x1 = r1; x2 = r2;
                        dst = (region == 0) ? g_q : g_k;
                    }
                    // pre-round to tf32 (rna) so attention's cp.async path is lossless
                    *(float2*)&dst[(size_t)((bb * NHEAD + h) * SEQ + ss) * HEAD_DIM + d] =
                        make_float2(tf32r(x1), tf32r(x2));
                }
            }
        }
    }
}

// ------------------------ attention v2 --------------------------------------
// 128 threads (4 warps), 64 q rows/CTA (16/warp). Q fragments in registers.
// K/V double-buffered via cp.async. P converted score->A fragment via shfl.
#define AT_KS 68
#define AT_VS 72
#define AT_STAGE (64 * AT_KS + 64 * AT_VS)      // floats per stage = 8960
#define AT_SMEM (2 * AT_STAGE * 4)              // 71680 bytes

__global__ __launch_bounds__(128, 3)
void attention_tf32_v2()
{
    extern __shared__ float sm[];
    const int tid = threadIdx.x;
    const int lane = tid & 31;
    const int w = tid >> 5;
    const int lr = lane >> 2;
    const int lc = lane & 3;
    const int bh = blockIdx.y;
    const int bb = bh >> 3, hh = bh & 7;
    const int row0 = blockIdx.x * 64;

    const float* qg = g_q + (size_t)bh * SEQ * HEAD_DIM;
    const float* kg = g_k + (size_t)bh * SEQ * HEAD_DIM;
    const float* vg = g_v + (size_t)bh * SEQ * HEAD_DIM;

    // ---- stage Q (scaled into log2 domain) through smem, extract fragments
    const float QSCALE = 0.125f * 1.44269504088896340736f;  // 1/sqrt(64) * log2(e)
#pragma unroll
    for (int i = 0; i < 8; i++) {
        int idx = tid + 128 * i;
        int row = idx >> 4, c4 = idx & 15;
        float4 v = *(const float4*)&qg[(size_t)(row0 + row) * HEAD_DIM + c4 * 4];
        v.x = tf32r(v.x * QSCALE); v.y = tf32r(v.y * QSCALE);
        v.z = tf32r(v.z * QSCALE); v.w = tf32r(v.w * QSCALE);
        *(float4*)&sm[row * AT_KS + c4 * 4] = v;
    }
    __syncthreads();

    const int r0 = w * 16 + lr;
    uint32_t qa[8][4];
#pragma unroll
    for (int kk = 0; kk < 8; kk++) {
        int kb = kk * 8;
        qa[kk][0] = __float_as_uint(sm[r0 * AT_KS + kb + lc]);
        qa[kk][1] = __float_as_uint(sm[(r0 + 8) * AT_KS + kb + lc]);
        qa[kk][2] = __float_as_uint(sm[r0 * AT_KS + kb + lc + 4]);
        qa[kk][3] = __float_as_uint(sm[(r0 + 8) * AT_KS + kb + lc + 4]);
    }
    __syncthreads();

    // ---- prefetch tile 0 into stage 0
    {
        float* Ksb = sm;
        float* Vsb = sm + 64 * AT_KS;
#pragma unroll
        for (int i = 0; i < 8; i++) {
            int idx = tid + 128 * i;
            int row = idx >> 4, c4 = idx & 15;
            CP_ASYNC16(smem_u32(&Ksb[row * AT_KS + c4 * 4]),
                       &kg[(size_t)row * HEAD_DIM + c4 * 4]);
            CP_ASYNC16(smem_u32(&Vsb[row * AT_VS + c4 * 4]),
                       &vg[(size_t)row * HEAD_DIM + c4 * 4]);
        }
        asm volatile("cp.async.commit_group;" ::: "memory");
    }

    float o[8][4];
#pragma unroll
    for (int nt = 0; nt < 8; nt++)
#pragma unroll
        for (int j = 0; j < 4; j++) o[nt][j] = 0.f;
    float m0 = -1e30f, m1 = -1e30f, l0 = 0.f, l1 = 0.f;

    const unsigned srcA = (lane & 28) | (lc >> 1);
    const unsigned srcB = srcA + 2;
    const bool odd = lc & 1;

    for (int t = 0; t < SEQ / 64; t++) {
        if (t < SEQ / 64 - 1) {
            float* Ksb = sm + ((t + 1) & 1) * AT_STAGE;
            float* Vsb = Ksb + 64 * AT_KS;
#pragma unroll
            for (int i = 0; i < 8; i++) {
                int idx = tid + 128 * i;
                int row = idx >> 4, c4 = idx & 15;
                CP_ASYNC16(smem_u32(&Ksb[row * AT_KS + c4 * 4]),
                           &kg[(size_t)((t + 1) * 64 + row) * HEAD_DIM + c4 * 4]);
                CP_ASYNC16(smem_u32(&Vsb[row * AT_VS + c4 * 4]),
                           &vg[(size_t)((t + 1) * 64 + row) * HEAD_DIM + c4 * 4]);
            }
            asm volatile("cp.async.commit_group;" ::: "memory");
            asm volatile("cp.async.wait_group 1;" ::: "memory");
        } else {
            asm volatile("cp.async.wait_group 0;" ::: "memory");
        }
        __syncthreads();

        const float* Ks = sm + (t & 1) * AT_STAGE;
        const float* Vs = Ks + 64 * AT_KS;

        // ---- scores (log2 domain): Sc[16 x 64] = Qs @ K^T
        float sc[8][4];
#pragma unroll
        for (int nt = 0; nt < 8; nt++)
#pragma unroll
            for (int j = 0; j < 4; j++) sc[nt][j] = 0.f;

#pragma unroll
        for (int kk = 0; kk < 8; kk++) {
            int kb = kk * 8;
#pragma unroll
            for (int nt = 0; nt < 8; nt++) {
                uint32_t b0 = __float_as_uint(Ks[(nt * 8 + lr) * AT_KS + kb + lc]);
                uint32_t b1 = __float_as_uint(Ks[(nt * 8 + lr) * AT_KS + kb + lc + 4]);
                mma_tf32(sc[nt], qa[kk], b0, b1);
            }
        }

        // ---- online softmax (base-2)
        float rmax0 = -1e30f, rmax1 = -1e30f;
#pragma unroll
        for (int nt = 0; nt < 8; nt++) {
            rmax0 = fmaxf(rmax0, fmaxf(sc[nt][0], sc[nt][1]));
            rmax1 = fmaxf(rmax1, fmaxf(sc[nt][2], sc[nt][3]));
        }
        rmax0 = fmaxf(rmax0, __shfl_xor_sync(0xffffffffu, rmax0, 1));
        rmax0 = fmaxf(rmax0, __shfl_xor_sync(0xffffffffu, rmax0, 2));
        rmax1 = fmaxf(rmax1, __shfl_xor_sync(0xffffffffu, rmax1, 1));
        rmax1 = fmaxf(rmax1, __shfl_xor_sync(0xffffffffu, rmax1, 2));

        float mn0 = fmaxf(m0, rmax0), mn1 = fmaxf(m1, rmax1);
        float corr0 = ex2f(m0 - mn0), corr1 = ex2f(m1 - mn1);
        float ls0 = 0.f, ls1 = 0.f;
#pragma unroll
        for (int nt = 0; nt < 8; nt++) {
            float p0 = ex2f(sc[nt][0] - mn0);
            float p1 = ex2f(sc[nt][1] - mn0);
            float p2 = ex2f(sc[nt][2] - mn1);
            float p3 = ex2f(sc[nt][3] - mn1);
            ls0 += p0 + p1;
            ls1 += p2 + p3;
            sc[nt][0] = tf32r(p0); sc[nt][1] = tf32r(p1);
            sc[nt][2] = tf32r(p2); sc[nt][3] = tf32r(p3);
        }
        ls0 += __shfl_xor_sync(0xffffffffu, ls0, 1);
        ls0 += __shfl_xor_sync(0xffffffffu, ls0, 2);
        ls1 += __shfl_xor_sync(0xffffffffu, ls1, 1);
        ls1 += __shfl_xor_sync(0xffffffffu, ls1, 2);
        l0 = l0 * corr0 + ls0;
        l1 = l1 * corr1 + ls1;
        m0 = mn0; m1 = mn1;
#pragma unroll
        for (int nt = 0; nt < 8; nt++) {
            o[nt][0] *= corr0; o[nt][1] *= corr0;
            o[nt][2] *= corr1; o[nt][3] *= corr1;
        }

        // ---- O += P @ V  (P fragment built from score fragment via shfl)
#pragma unroll
        for (int kk = 0; kk < 8; kk++) {
            float t0A = __shfl_sync(0xffffffffu, sc[kk][0], srcA);
            float t1A = __shfl_sync(0xffffffffu, sc[kk][1], srcA);
            float t2A = __shfl_sync(0xffffffffu, sc[kk][2], srcA);
            float t3A = __shfl_sync(0xffffffffu, sc[kk][3], srcA);
            float t0B = __shfl_sync(0xffffffffu, sc[kk][0], srcB);
            float t1B = __shfl_sync(0xffffffffu, sc[kk][1], srcB);
            float t2B = __shfl_sync(0xffffffffu, sc[kk][2], srcB);
            float t3B = __shfl_sync(0xffffffffu, sc[kk][3], srcB);
            uint32_t a[4];
            a[0] = __float_as_uint(odd ? t1A : t0A);
            a[1] = __float_as_uint(odd ? t3A : t2A);
            a[2] = __float_as_uint(odd ? t1B : t0B);
            a[3] = __float_as_uint(odd ? t3B : t2B);
            int kb = kk * 8;
#pragma unroll
            for (int nt = 0; nt < 8; nt++) {
                uint32_t b0 = __float_as_uint(Vs[(kb + lc) * AT_VS + nt * 8 + lr]);
                uint32_t b1 = __float_as_uint(Vs[(kb + lc + 4) * AT_VS + nt * 8 + lr]);
                mma_tf32(o[nt], a, b0, b1);
            }
        }
        __syncthreads();
    }

    // ---- epilogue: write [B,S,D]
    float il0 = 1.f / l0, il1 = 1.f / l1;
    int srow = row0 + r0;
#pragma unroll
    for (int nt = 0; nt < 8; nt++) {
        int d = hh * 64 + nt * 8 + 2 * lc;
        *(float2*)&g_att[(size_t)(bb * SEQ + srow) * D_MODEL + d] =
            make_float2(o[nt][0] * il0, o[nt][1] * il0);
        *(float2*)&g_att[(size_t)(bb * SEQ + srow + 8) * D_MODEL + d] =
            make_float2(o[nt][2] * il1, o[nt][3] * il1);
    }
}

// ------------------------ launch --------------------------------------------
extern "C" void kernel_launch(void* const* d_in, const int* in_sizes, int n_in,
                              void* d_out, int out_size)
{
    const float* x    = (const float*)d_in[0];
    const float* Wqkv = (const float*)d_in[1];
    const float* bqkv = (const float*)d_in[2];
    const float* Wo   = (const float*)d_in[3];
    const float* bo   = (const float*)d_in[4];
    float* out = (float*)d_out;

    float *p_att, *p_wqkvt, *p_wot;
    cudaGetSymbolAddress((void**)&p_att, g_att);
    cudaGetSymbolAddress((void**)&p_wqkvt, g_wqkvt);
    cudaGetSymbolAddress((void**)&p_wot, g_wot);

    // transpose weights -> [N][K]
    {
        dim3 blk(32, 8);
        transpose_kernel<<<dim3(QKV_N / 32, K_DIM / 32), blk>>>(Wqkv, p_wqkvt, K_DIM, QKV_N);
        transpose_kernel<<<dim3(D_MODEL / 32, K_DIM / 32), blk>>>(Wo, p_wot, K_DIM, D_MODEL);
    }
    // QKV projection + RoPE + split (+ tf32 pre-round)
    {
        dim3 grid(QKV_N / 128, M_ROWS / 128);
        gemm_tf32<1><<<grid, 256>>>(x, p_wqkvt, bqkv, nullptr, QKV_N);
    }
    // attention
    {
        cudaFuncSetAttribute(attention_tf32_v2,
                             cudaFuncAttributeMaxDynamicSharedMemorySize, AT_SMEM);
        dim3 grid(SEQ / 64, BATCH * NHEAD);
        attention_tf32_v2<<<grid, 128, AT_SMEM>>>();
    }
    // output projection
    {
        dim3 grid(D_MODEL / 128, M_ROWS / 128);
        gemm_tf32<0><<<grid, 256>>>(p_att, p_wot, bo, out, D_MODEL);
    }
}

// round 4
// speedup vs baseline: 4.7068x; 1.0803x over previous
#include <cuda_runtime.h>
#include <math.h>
#include <stdint.h>

#define BATCH 4
#define SEQ 2048
#define D_MODEL 512
#define NHEAD 8
#define HEAD_DIM 64
#define M_ROWS (BATCH * SEQ)      // 8192
#define QKV_N (3 * D_MODEL)       // 1536
#define K_DIM 512

// ------------------------ device scratch -----------------------------------
__device__ float g_q[BATCH * NHEAD * SEQ * HEAD_DIM];     // [B,H,S,Hd]
__device__ float g_k[BATCH * NHEAD * SEQ * HEAD_DIM];     // [B,H,S,Hd]
__device__ float g_vt[BATCH * NHEAD * HEAD_DIM * SEQ];    // [B,H,Hd,S] transposed
__device__ float g_att[M_ROWS * D_MODEL];                 // [B,S,D]
__device__ float g_wqkvt[QKV_N * K_DIM];                  // Wqkv^T
__device__ float g_wot[D_MODEL * D_MODEL];                // Wo^T

// ------------------------ helpers ------------------------------------------
__device__ __forceinline__ float tf32r(float x) {
    uint32_t u;
    asm("cvt.rna.tf32.f32 %0, %1;" : "=r"(u) : "f"(x));
    return __uint_as_float(u);
}

__device__ __forceinline__ float ex2f(float x) {
    float y;
    asm("ex2.approx.f32 %0, %1;" : "=f"(y) : "f"(x));
    return y;
}

__device__ __forceinline__ void mma_tf32(float c[4], const uint32_t a[4],
                                         uint32_t b0, uint32_t b1) {
    asm volatile(
        "mma.sync.aligned.m16n8k8.row.col.f32.tf32.tf32.f32 "
        "{%0,%1,%2,%3}, {%4,%5,%6,%7}, {%8,%9}, {%0,%1,%2,%3};\n"
        : "+f"(c[0]), "+f"(c[1]), "+f"(c[2]), "+f"(c[3])
        : "r"(a[0]), "r"(a[1]), "r"(a[2]), "r"(a[3]), "r"(b0), "r"(b1));
}

__device__ __forceinline__ unsigned smem_u32(const void* p) {
    return (unsigned)__cvta_generic_to_shared(p);
}

#define CP_ASYNC16(dst_u32, src_ptr) \
    asm volatile("cp.async.cg.shared.global [%0], [%1], 16;\n" \
                 :: "r"(dst_u32), "l"(src_ptr) : "memory")

// ------------------------ transpose: in[R][C] -> out[C][R] ------------------
__global__ __launch_bounds__(256)
void transpose_kernel(const float* __restrict__ in, float* __restrict__ out,
                      int R, int C)
{
    __shared__ float tile[32][33];
    int cBase = blockIdx.x * 32, rBase = blockIdx.y * 32;
    int tx = threadIdx.x, ty = threadIdx.y;
#pragma unroll
    for (int i = 0; i < 32; i += 8)
        tile[ty + i][tx] = in[(size_t)(rBase + ty + i) * C + cBase + tx];
    __syncthreads();
#pragma unroll
    for (int i = 0; i < 32; i += 8)
        out[(size_t)(cBase + ty + i) * R + rBase + tx] = tile[tx][ty + i];
}

// ------------------------ tf32 GEMM ----------------------------------------
// MODE 0: plain store. MODE 1: QKV epilogue (RoPE q/k, V transposed store).
template <int MODE>
__global__ __launch_bounds__(256, 2)
void gemm_tf32(const float* __restrict__ A, const float* __restrict__ Bt,
               const float* __restrict__ bias, float* __restrict__ C, int N)
{
    __shared__ float As[128][36];
    __shared__ float Bs[128][36];

    const int tid = threadIdx.x;
    const int lane = tid & 31;
    const int warp = tid >> 5;
    const int wm = warp >> 2;
    const int wn = warp & 3;
    const int lr = lane >> 2;
    const int lc = lane & 3;
    const int mBase = blockIdx.y * 128;
    const int nBase = blockIdx.x * 128;

    float acc[4][4][4];
#pragma unroll
    for (int mt = 0; mt < 4; mt++)
#pragma unroll
        for (int nt = 0; nt < 4; nt++)
#pragma unroll
            for (int j = 0; j < 4; j++) acc[mt][nt][j] = 0.f;

    const int cpRow = tid >> 3;
    const int cpC4 = tid & 7;

    for (int k0 = 0; k0 < K_DIM; k0 += 32) {
        __syncthreads();
#pragma unroll
        for (int i = 0; i < 4; i++) {
            int row = cpRow + i * 32;
            float4 va = *(const float4*)&A[(size_t)(mBase + row) * K_DIM + k0 + cpC4 * 4];
            va.x = tf32r(va.x); va.y = tf32r(va.y); va.z = tf32r(va.z); va.w = tf32r(va.w);
            *(float4*)&As[row][cpC4 * 4] = va;
            float4 vb = *(const float4*)&Bt[(size_t)(nBase + row) * K_DIM + k0 + cpC4 * 4];
            vb.x = tf32r(vb.x); vb.y = tf32r(vb.y); vb.z = tf32r(vb.z); vb.w = tf32r(vb.w);
            *(float4*)&Bs[row][cpC4 * 4] = vb;
        }
        __syncthreads();

#pragma unroll
        for (int kk = 0; kk < 4; kk++) {
            const int kb = kk * 8;
            uint32_t af[4][4];
#pragma unroll
            for (int mt = 0; mt < 4; mt++) {
                int r = wm * 64 + mt * 16 + lr;
                af[mt][0] = __float_as_uint(As[r][kb + lc]);
                af[mt][1] = __float_as_uint(As[r + 8][kb + lc]);
                af[mt][2] = __float_as_uint(As[r][kb + lc + 4]);
                af[mt][3] = __float_as_uint(As[r + 8][kb + lc + 4]);
            }
#pragma unroll
            for (int nt = 0; nt < 4; nt++) {
                int cn = wn * 32 + nt * 8 + lr;
                uint32_t b0 = __float_as_uint(Bs[cn][kb + lc]);
                uint32_t b1 = __float_as_uint(Bs[cn][kb + lc + 4]);
#pragma unroll
                for (int mt = 0; mt < 4; mt++)
                    mma_tf32(acc[mt][nt], af[mt], b0, b1);
            }
        }
    }

#pragma unroll
    for (int mt = 0; mt < 4; mt++) {
#pragma unroll
        for (int nt = 0; nt < 4; nt++) {
            int grow0 = mBase + wm * 64 + mt * 16 + lr;
            int gcol = nBase + wn * 32 + nt * 8 + 2 * lc;
            float b0v = bias[gcol], b1v = bias[gcol + 1];
            if (MODE == 0) {
                *(float2*)&C[(size_t)grow0 * N + gcol] =
                    make_float2(acc[mt][nt][0] + b0v, acc[mt][nt][1] + b1v);
                *(float2*)&C[(size_t)(grow0 + 8) * N + gcol] =
                    make_float2(acc[mt][nt][2] + b0v, acc[mt][nt][3] + b1v);
            } else {
                int region = gcol >> 9;          // 0=q, 1=k, 2=v
                int h = (gcol >> 6) & 7;
                int d = gcol & 63;               // even
#pragma unroll
                for (int rr = 0; rr < 2; rr++) {
                    int grow = grow0 + rr * 8;
                    int bb = grow >> 11;
                    int ss = grow & (SEQ - 1);
                    float x1 = acc[mt][nt][2 * rr] + b0v;
                    float x2 = acc[mt][nt][2 * rr + 1] + b1v;
                    if (region == 2) {
                        // V: transposed store [B,H,Hd,S], tf32 pre-rounded
                        size_t base = ((size_t)(bb * NHEAD + h) * HEAD_DIM + d) * SEQ + ss;
                        g_vt[base] = tf32r(x1);
                        g_vt[base + SEQ] = tf32r(x2);
                    } else {
                        float inv_freq = __powf(10000.f, -(float)d * (1.f / 64.f));
                        float sn, cs;
                        __sincosf((float)ss * inv_freq, &sn, &cs);
                        float r1 = x1 * cs - x2 * sn;
                        float r2 = x1 * sn + x2 * cs;
                        float* dst = (region == 0) ? g_q : g_k;
                        *(float2*)&dst[(size_t)((bb * NHEAD + h) * SEQ + ss) * HEAD_DIM + d] =
                            make_float2(tf32r(r1), tf32r(r2));
                    }
                }
            }
        }
    }
}

// ------------------------ attention v3 --------------------------------------
// 128 threads (4 warps), 128 q rows/CTA (32/warp, two m16 tiles).
// k-slot permutation: slot lc <-> elem 2lc, slot lc+4 <-> elem 2lc+1.
// -> B fragments are float2 LDS; score output frag == PV A frag (no shfl).
#define AT_S 68
#define AT_STAGE (2 * 64 * AT_S)            // K tile + VT tile (floats) = 8704
#define AT_SMEM (2 * AT_STAGE * 4)          // 69632 bytes

__global__ __launch_bounds__(128, 2)
void attention_tf32_v3()
{
    extern __shared__ float sm[];
    const int tid = threadIdx.x;
    const int lane = tid & 31;
    const int w = tid >> 5;
    const int lr = lane >> 2;
    const int lc = lane & 3;
    const int bh = blockIdx.y;
    const int bb = bh >> 3, hh = bh & 7;
    const int row0 = blockIdx.x * 128;

    const float* qg = g_q + (size_t)bh * SEQ * HEAD_DIM;
    const float* kg = g_k + (size_t)bh * SEQ * HEAD_DIM;
    const float* vtg = g_vt + (size_t)bh * HEAD_DIM * SEQ;

    // ---- stage Q (scaled into log2 domain), extract permuted fragments
    const float QSCALE = 0.125f * 1.44269504088896340736f;  // 1/8 * log2(e)
#pragma unroll
    for (int i = 0; i < 16; i++) {
        int idx = tid + 128 * i;
        int row = idx >> 4, c4 = idx & 15;
        float4 v = *(const float4*)&qg[(size_t)(row0 + row) * HEAD_DIM + c4 * 4];
        v.x = tf32r(v.x * QSCALE); v.y = tf32r(v.y * QSCALE);
        v.z = tf32r(v.z * QSCALE); v.w = tf32r(v.w * QSCALE);
        *(float4*)&sm[row * AT_S + c4 * 4] = v;
    }
    __syncthreads();

    const int r0 = w * 32 + lr;          // warp's first row
    uint32_t qa[8][8];                   // [kk][tile0: a0..a3, tile1: a0..a3]
#pragma unroll
    for (int kk = 0; kk < 8; kk++) {
        int col = kk * 8 + 2 * lc;
        float2 f0 = *(const float2*)&sm[(r0) * AT_S + col];
        float2 f1 = *(const float2*)&sm[(r0 + 8) * AT_S + col];
        float2 f2 = *(const float2*)&sm[(r0 + 16) * AT_S + col];
        float2 f3 = *(const float2*)&sm[(r0 + 24) * AT_S + col];
        qa[kk][0] = __float_as_uint(f0.x); qa[kk][2] = __float_as_uint(f0.y);
        qa[kk][1] = __float_as_uint(f1.x); qa[kk][3] = __float_as_uint(f1.y);
        qa[kk][4] = __float_as_uint(f2.x); qa[kk][6] = __float_as_uint(f2.y);
        qa[kk][5] = __float_as_uint(f3.x); qa[kk][7] = __float_as_uint(f3.y);
    }
    __syncthreads();

    // ---- prefetch tile 0
    {
        float* Ksb = sm;
        float* Vsb = sm + 64 * AT_S;
#pragma unroll
        for (int i = 0; i < 8; i++) {
            int idx = tid + 128 * i;
            int row = idx >> 4, c4 = idx & 15;
            CP_ASYNC16(smem_u32(&Ksb[row * AT_S + c4 * 4]),
                       &kg[(size_t)row * HEAD_DIM + c4 * 4]);
            CP_ASYNC16(smem_u32(&Vsb[row * AT_S + c4 * 4]),
                       &vtg[(size_t)row * SEQ + c4 * 4]);
        }
        asm volatile("cp.async.commit_group;" ::: "memory");
    }

    float o[2][8][4];
#pragma unroll
    for (int mt = 0; mt < 2; mt++)
#pragma unroll
        for (int nt = 0; nt < 8; nt++)
#pragma unroll
            for (int j = 0; j < 4; j++) o[mt][nt][j] = 0.f;
    float m[4] = {-1e30f, -1e30f, -1e30f, -1e30f};
    float l[4] = {0.f, 0.f, 0.f, 0.f};

    for (int t = 0; t < SEQ / 64; t++) {
        if (t < SEQ / 64 - 1) {
            float* Ksb = sm + ((t + 1) & 1) * AT_STAGE;
            float* Vsb = Ksb + 64 * AT_S;
#pragma unroll
            for (int i = 0; i < 8; i++) {
                int idx = tid + 128 * i;
                int row = idx >> 4, c4 = idx & 15;
                CP_ASYNC16(smem_u32(&Ksb[row * AT_S + c4 * 4]),
                           &kg[(size_t)((t + 1) * 64 + row) * HEAD_DIM + c4 * 4]);
                CP_ASYNC16(smem_u32(&Vsb[row * AT_S + c4 * 4]),
                           &vtg[(size_t)row * SEQ + (t + 1) * 64 + c4 * 4]);
            }
            asm volatile("cp.async.commit_group;" ::: "memory");
            asm volatile("cp.async.wait_group 1;" ::: "memory");
        } else {
            asm volatile("cp.async.wait_group 0;" ::: "memory");
        }
        __syncthreads();

        const float* Ks = sm + (t & 1) * AT_STAGE;
        const float* Vs = Ks + 64 * AT_S;

        // ---- scores: Sc[32 x 64] = Qs @ K^T (permuted k-slots, float2 B)
        float sc[2][8][4];
#pragma unroll
        for (int mt = 0; mt < 2; mt++)
#pragma unroll
            for (int nt = 0; nt < 8; nt++)
#pragma unroll
                for (int j = 0; j < 4; j++) sc[mt][nt][j] = 0.f;

#pragma unroll
        for (int kk = 0; kk < 8; kk++) {
            int col = kk * 8 + 2 * lc;
#pragma unroll
            for (int nt = 0; nt < 8; nt++) {
                float2 b = *(const float2*)&Ks[(nt * 8 + lr) * AT_S + col];
                uint32_t b0 = __float_as_uint(b.x), b1 = __float_as_uint(b.y);
                mma_tf32(sc[0][nt], &qa[kk][0], b0, b1);
                mma_tf32(sc[1][nt], &qa[kk][4], b0, b1);
            }
        }

        // ---- online softmax (base-2), per m-tile
#pragma unroll
        for (int mt = 0; mt < 2; mt++) {
            float rmax0 = -1e30f, rmax1 = -1e30f;
#pragma unroll
            for (int nt = 0; nt < 8; nt++) {
                rmax0 = fmaxf(rmax0, fmaxf(sc[mt][nt][0], sc[mt][nt][1]));
                rmax1 = fmaxf(rmax1, fmaxf(sc[mt][nt][2], sc[mt][nt][3]));
            }
            rmax0 = fmaxf(rmax0, __shfl_xor_sync(0xffffffffu, rmax0, 1));
            rmax0 = fmaxf(rmax0, __shfl_xor_sync(0xffffffffu, rmax0, 2));
            rmax1 = fmaxf(rmax1, __shfl_xor_sync(0xffffffffu, rmax1, 1));
            rmax1 = fmaxf(rmax1, __shfl_xor_sync(0xffffffffu, rmax1, 2));

            float mn0 = fmaxf(m[2 * mt], rmax0);
            float mn1 = fmaxf(m[2 * mt + 1], rmax1);
            float corr0 = ex2f(m[2 * mt] - mn0);
            float corr1 = ex2f(m[2 * mt + 1] - mn1);
            float ls0 = 0.f, ls1 = 0.f;
#pragma unroll
            for (int nt = 0; nt < 8; nt++) {
                float p0 = ex2f(sc[mt][nt][0] - mn0);
                float p1 = ex2f(sc[mt][nt][1] - mn0);
                float p2 = ex2f(sc[mt][nt][2] - mn1);
                float p3 = ex2f(sc[mt][nt][3] - mn1);
                ls0 += p0 + p1;
                ls1 += p2 + p3;
                sc[mt][nt][0] = tf32r(p0); sc[mt][nt][1] = tf32r(p1);
                sc[mt][nt][2] = tf32r(p2); sc[mt][nt][3] = tf32r(p3);
            }
            ls0 += __shfl_xor_sync(0xffffffffu, ls0, 1);
            ls0 += __shfl_xor_sync(0xffffffffu, ls0, 2);
            ls1 += __shfl_xor_sync(0xffffffffu, ls1, 1);
            ls1 += __shfl_xor_sync(0xffffffffu, ls1, 2);
            l[2 * mt] = l[2 * mt] * corr0 + ls0;
            l[2 * mt + 1] = l[2 * mt + 1] * corr1 + ls1;
            m[2 * mt] = mn0; m[2 * mt + 1] = mn1;
#pragma unroll
            for (int nt = 0; nt < 8; nt++) {
                o[mt][nt][0] *= corr0; o[mt][nt][1] *= corr0;
                o[mt][nt][2] *= corr1; o[mt][nt][3] *= corr1;
            }
        }

        // ---- O += P @ V (score frag IS the A frag under slot permutation)
#pragma unroll
        for (int kk = 0; kk < 8; kk++) {
            uint32_t a0[4], a1[4];
            a0[0] = __float_as_uint(sc[0][kk][0]);
            a0[1] = __float_as_uint(sc[0][kk][2]);
            a0[2] = __float_as_uint(sc[0][kk][1]);
            a0[3] = __float_as_uint(sc[0][kk][3]);
            a1[0] = __float_as_uint(sc[1][kk][0]);
            a1[1] = __float_as_uint(sc[1][kk][2]);
            a1[2] = __float_as_uint(sc[1][kk][1]);
            a1[3] = __float_as_uint(sc[1][kk][3]);
            int col = kk * 8 + 2 * lc;
#pragma unroll
            for (int nt = 0; nt < 8; nt++) {
                float2 b = *(const float2*)&Vs[(nt * 8 + lr) * AT_S + col];
                uint32_t b0 = __float_as_uint(b.x), b1 = __float_as_uint(b.y);
                mma_tf32(o[0][nt], a0, b0, b1);
                mma_tf32(o[1][nt], a1, b0, b1);
            }
        }
        __syncthreads();
    }

    // ---- epilogue: write [B,S,D]
#pragma unroll
    for (int mt = 0; mt < 2; mt++) {
        float il0 = 1.f / l[2 * mt], il1 = 1.f / l[2 * mt + 1];
        int srow = row0 + w * 32 + mt * 16 + lr;
#pragma unroll
        for (int nt = 0; nt < 8; nt++) {
            int d = hh * 64 + nt * 8 + 2 * lc;
            *(float2*)&g_att[(size_t)(bb * SEQ + srow) * D_MODEL + d] =
                make_float2(o[mt][nt][0] * il0, o[mt][nt][1] * il0);
            *(float2*)&g_att[(size_t)(bb * SEQ + srow + 8) * D_MODEL + d] =
                make_float2(o[mt][nt][2] * il1, o[mt][nt][3] * il1);
        }
    }
}

// ------------------------ launch --------------------------------------------
extern "C" void kernel_launch(void* const* d_in, const int* in_sizes, int n_in,
                              void* d_out, int out_size)
{
    const float* x    = (const float*)d_in[0];
    const float* Wqkv = (const float*)d_in[1];
    const float* bqkv = (const float*)d_in[2];
    const float* Wo   = (const float*)d_in[3];
    const float* bo   = (const float*)d_in[4];
    float* out = (float*)d_out;

    float *p_att, *p_wqkvt, *p_wot;
    cudaGetSymbolAddress((void**)&p_att, g_att);
    cudaGetSymbolAddress((void**)&p_wqkvt, g_wqkvt);
    cudaGetSymbolAddress((void**)&p_wot, g_wot);

    // transpose weights -> [N][K]
    {
        dim3 blk(32, 8);
        transpose_kernel<<<dim3(QKV_N / 32, K_DIM / 32), blk>>>(Wqkv, p_wqkvt, K_DIM, QKV_N);
        transpose_kernel<<<dim3(D_MODEL / 32, K_DIM / 32), blk>>>(Wo, p_wot, K_DIM, D_MODEL);
    }
    // QKV projection + RoPE + split (+ tf32 pre-round, V transposed)
    {
        dim3 grid(QKV_N / 128, M_ROWS / 128);
        gemm_tf32<1><<<grid, 256>>>(x, p_wqkvt, bqkv, nullptr, QKV_N);
    }
    // attention
    {
        cudaFuncSetAttribute(attention_tf32_v3,
                             cudaFuncAttributeMaxDynamicSharedMemorySize, AT_SMEM);
        dim3 grid(SEQ / 128, BATCH * NHEAD);
        attention_tf32_v3<<<grid, 128, AT_SMEM>>>();
    }
    // output projection
    {
        dim3 grid(D_MODEL / 128, M_ROWS / 128);
        gemm_tf32<0><<<grid, 256>>>(p_att, p_wot, bo, out, D_MODEL);
    }
}